// round 2
// baseline (speedup 1.0000x reference)
#include <cuda_runtime.h>
#include <math.h>

#define BB  2
#define SSL 2048
#define DD  1024
#define HH  16
#define HDD 64
#define MSZ (BB*SSL)

// Scratch (allocation-free rule: device globals)
__device__ float g_q[MSZ*DD];
__device__ float g_kt[MSZ*DD];   // holds raw K after proj, softplus(K) after fuse
__device__ float g_v[MSZ*DD];

// ---------------------------------------------------------------------------
// Projection GEMM: out = X @ W + b.  blockIdx.z: 0 -> (Wq,bq)->g_q, 1 -> (Wk,bk)->g_kt
// 64x64 tile, 256 threads, 4x4 per-thread microtile, k-tile 16.
// ---------------------------------------------------------------------------
__global__ __launch_bounds__(256) void proj_kernel(
    const float* __restrict__ X,
    const float* __restrict__ Wq, const float* __restrict__ bq,
    const float* __restrict__ Wk, const float* __restrict__ bk)
{
    const float* W   = (blockIdx.z == 0) ? Wq : Wk;
    const float* bia = (blockIdx.z == 0) ? bq : bk;
    float*       out = (blockIdx.z == 0) ? g_q : g_kt;

    __shared__ float As[16][65];   // [k][m], stride 65 -> conflict-free transpose store
    __shared__ float Bs[16][64];   // [k][n]

    const int m0 = blockIdx.y * 64;
    const int n0 = blockIdx.x * 64;
    const int t  = threadIdx.x;
    const int tx = t & 15, ty = t >> 4;
    const int lrow = t >> 2, lv = t & 3;    // X-tile: 64 rows x 4 float4
    const int wrow = t >> 4, wv = t & 15;   // W-tile: 16 rows x 16 float4

    float acc[4][4] = {};

    for (int k0 = 0; k0 < DD; k0 += 16) {
        float4 x4 = *(const float4*)(X + (size_t)(m0 + lrow) * DD + k0 + 4*lv);
        float4 w4 = *(const float4*)(W + (size_t)(k0 + wrow) * DD + n0 + 4*wv);
        As[4*lv+0][lrow] = x4.x;
        As[4*lv+1][lrow] = x4.y;
        As[4*lv+2][lrow] = x4.z;
        As[4*lv+3][lrow] = x4.w;
        *(float4*)&Bs[wrow][4*wv] = w4;
        __syncthreads();
        #pragma unroll
        for (int kk = 0; kk < 16; kk++) {
            float a0 = As[kk][4*ty+0], a1 = As[kk][4*ty+1];
            float a2 = As[kk][4*ty+2], a3 = As[kk][4*ty+3];
            float4 b4 = *(const float4*)&Bs[kk][4*tx];
            acc[0][0] += a0*b4.x; acc[0][1] += a0*b4.y; acc[0][2] += a0*b4.z; acc[0][3] += a0*b4.w;
            acc[1][0] += a1*b4.x; acc[1][1] += a1*b4.y; acc[1][2] += a1*b4.z; acc[1][3] += a1*b4.w;
            acc[2][0] += a2*b4.x; acc[2][1] += a2*b4.y; acc[2][2] += a2*b4.z; acc[2][3] += a2*b4.w;
            acc[3][0] += a3*b4.x; acc[3][1] += a3*b4.y; acc[3][2] += a3*b4.z; acc[3][3] += a3*b4.w;
        }
        __syncthreads();
    }
    float4 bv = *(const float4*)(bia + n0 + 4*tx);
    #pragma unroll
    for (int i = 0; i < 4; i++) {
        float4 o;
        o.x = acc[i][0] + bv.x;
        o.y = acc[i][1] + bv.y;
        o.z = acc[i][2] + bv.z;
        o.w = acc[i][3] + bv.w;
        *(float4*)(out + (size_t)(m0 + 4*ty + i) * DD + n0 + 4*tx) = o;
    }
}

// ---------------------------------------------------------------------------
// Elementwise: kt = softplus(k_raw), v = q + k_raw   (k_t = -log_sigmoid(-k))
// ---------------------------------------------------------------------------
__device__ __forceinline__ float softplus_f(float x) {
    return (x > 15.0f) ? x : log1pf(__expf(x));
}

__global__ __launch_bounds__(256) void fuse_kernel()
{
    int i = blockIdx.x * 256 + threadIdx.x;       // over MSZ*DD/4 float4s
    float4 q = ((const float4*)g_q)[i];
    float4 k = ((const float4*)g_kt)[i];
    float4 v, kt;
    v.x = q.x + k.x;  v.y = q.y + k.y;  v.z = q.z + k.z;  v.w = q.w + k.w;
    kt.x = softplus_f(k.x);
    kt.y = softplus_f(k.y);
    kt.z = softplus_f(k.z);
    kt.w = softplus_f(k.w);
    ((float4*)g_v)[i]  = v;
    ((float4*)g_kt)[i] = kt;
}

// ---------------------------------------------------------------------------
// Flash attention: block = (64-query tile, head, batch). 256 threads.
// QsT/KsT dim-major stride 65; Vs/Ss stride 68 (float4). Online softmax,
// 4 threads per row. Query-axis mask -> row forced to -10000 (exactly uniform
// softmax, matching reference).
// Tile loads: 64 rows x 16 float4 = 1024 float4s -> 4 float4s per thread.
// ---------------------------------------------------------------------------
#define PADA 65
#define PADB 68
#define SM_FLOATS (64*PADA*2 + 64*PADB*2 + 64*3)
#define SMEM_ATTN (SM_FLOATS*4 + 64*4)

__global__ __launch_bounds__(256) void attn_kernel(
    const int* __restrict__ amask, float* __restrict__ out)
{
    extern __shared__ float sm[];
    float* QsT = sm;                  // [64][PADA]  dim-major, pre-scaled by 1/8
    float* KsT = QsT + 64*PADA;       // [64][PADA]  dim-major
    float* Vs  = KsT + 64*PADA;       // [64][PADB]  key-major
    float* Ss  = Vs  + 64*PADB;       // [64][PADB]  query-major scores/probs
    float* msh = Ss  + 64*PADB;       // [64] running max
    float* lsh = msh + 64;            // [64] running sum
    float* csh = lsh + 64;            // [64] correction factor
    int*   mkf = (int*)(csh + 64);    // [64] masked-row flag

    const int qt = blockIdx.x, h = blockIdx.y, b = blockIdx.z;
    const int t  = threadIdx.x;
    const int tx = t & 15, ty = t >> 4;
    const int lrow = t >> 2, lv = t & 3;

    if (t < 64) {
        msh[t] = -1e30f;
        lsh[t] = 0.0f;
        mkf[t] = (amask[b*SSL + qt*64 + t] == 0) ? 1 : 0;
    }
    {   // load Q tile transposed (full 64x64), fold 1/sqrt(HD)=1/8
        const float* qp = g_q + ((size_t)(b*SSL + qt*64 + lrow))*DD + h*HDD;
        #pragma unroll
        for (int j = 0; j < 4; j++) {
            int c = lv + 4*j;                       // float4 column 0..15
            float4 q4 = *(const float4*)(qp + 4*c);
            QsT[(4*c+0)*PADA + lrow] = q4.x * 0.125f;
            QsT[(4*c+1)*PADA + lrow] = q4.y * 0.125f;
            QsT[(4*c+2)*PADA + lrow] = q4.z * 0.125f;
            QsT[(4*c+3)*PADA + lrow] = q4.w * 0.125f;
        }
    }
    float accO[4][4] = {};
    __syncthreads();

    for (int k0 = 0; k0 < SSL; k0 += 64) {
        {   // load K (transposed) and V tiles, full 64x64 each
            size_t base = ((size_t)(b*SSL + k0 + lrow))*DD + h*HDD;
            #pragma unroll
            for (int j = 0; j < 4; j++) {
                int c = lv + 4*j;
                float4 k4 = *(const float4*)(g_kt + base + 4*c);
                KsT[(4*c+0)*PADA + lrow] = k4.x;
                KsT[(4*c+1)*PADA + lrow] = k4.y;
                KsT[(4*c+2)*PADA + lrow] = k4.z;
                KsT[(4*c+3)*PADA + lrow] = k4.w;
                float4 v4 = *(const float4*)(g_v + base + 4*c);
                *(float4*)&Vs[lrow*PADB + 4*c] = v4;
            }
        }
        __syncthreads();

        // S tile = (Q/8) @ K^T
        float accS[4][4] = {};
        #pragma unroll 8
        for (int kk = 0; kk < 64; kk++) {
            float a0 = QsT[kk*PADA + 4*ty+0], a1 = QsT[kk*PADA + 4*ty+1];
            float a2 = QsT[kk*PADA + 4*ty+2], a3 = QsT[kk*PADA + 4*ty+3];
            float b0 = KsT[kk*PADA + 4*tx+0], b1 = KsT[kk*PADA + 4*tx+1];
            float b2 = KsT[kk*PADA + 4*tx+2], b3 = KsT[kk*PADA + 4*tx+3];
            accS[0][0] += a0*b0; accS[0][1] += a0*b1; accS[0][2] += a0*b2; accS[0][3] += a0*b3;
            accS[1][0] += a1*b0; accS[1][1] += a1*b1; accS[1][2] += a1*b2; accS[1][3] += a1*b3;
            accS[2][0] += a2*b0; accS[2][1] += a2*b1; accS[2][2] += a2*b2; accS[2][3] += a2*b3;
            accS[3][0] += a3*b0; accS[3][1] += a3*b1; accS[3][2] += a3*b2; accS[3][3] += a3*b3;
        }
        #pragma unroll
        for (int i = 0; i < 4; i++)
            *(float4*)&Ss[(4*ty+i)*PADB + 4*tx] =
                make_float4(accS[i][0], accS[i][1], accS[i][2], accS[i][3]);
        __syncthreads();

        // Online softmax: 4 threads per row, 16 cols each
        {
            const int r = t >> 2, c4 = t & 3;
            const bool masked = (mkf[r] != 0);
            float sv[16], mx = -1e30f;
            #pragma unroll
            for (int ii = 0; ii < 16; ii++) {
                float s = Ss[r*PADB + c4*16 + ii];
                if (masked) s = -10000.0f;
                sv[ii] = s;
                mx = fmaxf(mx, s);
            }
            mx = fmaxf(mx, __shfl_xor_sync(0xffffffffu, mx, 1));
            mx = fmaxf(mx, __shfl_xor_sync(0xffffffffu, mx, 2));
            float mold = msh[r];
            float mnew = fmaxf(mold, mx);
            float sum = 0.0f;
            #pragma unroll
            for (int ii = 0; ii < 16; ii++) {
                float p = __expf(sv[ii] - mnew);
                Ss[r*PADB + c4*16 + ii] = p;
                sum += p;
            }
            sum += __shfl_xor_sync(0xffffffffu, sum, 1);
            sum += __shfl_xor_sync(0xffffffffu, sum, 2);
            if (c4 == 0) {
                float corr = __expf(mold - mnew);   // first tile: exp(-inf)=0
                csh[r] = corr;
                msh[r] = mnew;
                lsh[r] = lsh[r] * corr + sum;
            }
        }
        __syncthreads();

        // Rescale O and accumulate P @ V
        {
            float cr0 = csh[4*ty+0], cr1 = csh[4*ty+1];
            float cr2 = csh[4*ty+2], cr3 = csh[4*ty+3];
            #pragma unroll
            for (int j = 0; j < 4; j++) {
                accO[0][j] *= cr0; accO[1][j] *= cr1;
                accO[2][j] *= cr2; accO[3][j] *= cr3;
            }
        }
        #pragma unroll 8
        for (int kk = 0; kk < 64; kk++) {
            float a0 = Ss[(4*ty+0)*PADB + kk], a1 = Ss[(4*ty+1)*PADB + kk];
            float a2 = Ss[(4*ty+2)*PADB + kk], a3 = Ss[(4*ty+3)*PADB + kk];
            float4 b4 = *(const float4*)&Vs[kk*PADB + 4*tx];
            accO[0][0] += a0*b4.x; accO[0][1] += a0*b4.y; accO[0][2] += a0*b4.z; accO[0][3] += a0*b4.w;
            accO[1][0] += a1*b4.x; accO[1][1] += a1*b4.y; accO[1][2] += a1*b4.z; accO[1][3] += a1*b4.w;
            accO[2][0] += a2*b4.x; accO[2][1] += a2*b4.y; accO[2][2] += a2*b4.z; accO[2][3] += a2*b4.w;
            accO[3][0] += a3*b4.x; accO[3][1] += a3*b4.y; accO[3][2] += a3*b4.z; accO[3][3] += a3*b4.w;
        }
        __syncthreads();
    }

    // Final: O / l, write [B,S,H*HD]
    float li[4];
    li[0] = 1.0f / lsh[4*ty+0];
    li[1] = 1.0f / lsh[4*ty+1];
    li[2] = 1.0f / lsh[4*ty+2];
    li[3] = 1.0f / lsh[4*ty+3];
    #pragma unroll
    for (int i = 0; i < 4; i++) {
        float4 o;
        o.x = accO[i][0] * li[i];
        o.y = accO[i][1] * li[i];
        o.z = accO[i][2] * li[i];
        o.w = accO[i][3] * li[i];
        *(float4*)(out + ((size_t)(b*SSL + qt*64 + 4*ty + i))*DD + h*HDD + 4*tx) = o;
    }
}

// ---------------------------------------------------------------------------
extern "C" void kernel_launch(void* const* d_in, const int* in_sizes, int n_in,
                              void* d_out, int out_size)
{
    const float* X     = (const float*)d_in[0];   // hidden_states [2,2048,1024]
    const int*   amask = (const int*)  d_in[1];   // attention_mask [2,2048]
    const float* Wq    = (const float*)d_in[2];
    const float* bq    = (const float*)d_in[3];
    const float* Wk    = (const float*)d_in[4];
    const float* bk    = (const float*)d_in[5];
    float*       out   = (float*)d_out;

    proj_kernel<<<dim3(DD/64, MSZ/64, 2), 256>>>(X, Wq, bq, Wk, bk);
    fuse_kernel<<<(MSZ*DD/4)/256, 256>>>();
    cudaFuncSetAttribute(attn_kernel,
                         cudaFuncAttributeMaxDynamicSharedMemorySize, SMEM_ATTN);
    attn_kernel<<<dim3(SSL/64, HH, BB), 256, SMEM_ATTN>>>(amask, out);
}

// round 3
// speedup vs baseline: 2.2019x; 2.2019x over previous
#include <cuda_runtime.h>
#include <math.h>
#include <stdint.h>

#define BB  2
#define SSL 2048
#define DD  1024
#define HH  16
#define HDD 64
#define MSZ (BB*SSL)

// Scratch (allocation-free rule: device globals)
__device__ float g_q[MSZ*DD];
__device__ float g_kt[MSZ*DD];   // raw K after proj, softplus(K) after fuse
__device__ float g_v[MSZ*DD];

// ---------------------------------------------------------------------------
// tf32 helpers
// ---------------------------------------------------------------------------
__device__ __forceinline__ uint32_t f2tf32(float x) {
    uint32_t r;
    asm("cvt.rna.tf32.f32 %0, %1;" : "=r"(r) : "f"(x));
    return r;
}

__device__ __forceinline__ void mma_tf32(float c[4], const uint32_t a[4],
                                         uint32_t b0, uint32_t b1) {
    asm volatile(
        "mma.sync.aligned.m16n8k8.row.col.f32.tf32.tf32.f32 "
        "{%0,%1,%2,%3}, {%4,%5,%6,%7}, {%8,%9}, {%0,%1,%2,%3};"
        : "+f"(c[0]), "+f"(c[1]), "+f"(c[2]), "+f"(c[3])
        : "r"(a[0]), "r"(a[1]), "r"(a[2]), "r"(a[3]), "r"(b0), "r"(b1));
}

// ---------------------------------------------------------------------------
// Projection GEMM (tf32 tensor): out = X @ W + b.
// CTA 128x128, k-tile 32, 8 warps as 4m x 2n, warp tile 32x64.
// Xs stride 36, Ws stride 136 -> conflict-free fragment loads.
// ---------------------------------------------------------------------------
#define XS_STR 36
#define WS_STR 136

__global__ __launch_bounds__(256) void proj_tc(
    const float* __restrict__ X,
    const float* __restrict__ Wq, const float* __restrict__ bq,
    const float* __restrict__ Wk, const float* __restrict__ bk)
{
    const float* W   = (blockIdx.z == 0) ? Wq : Wk;
    const float* bia = (blockIdx.z == 0) ? bq : bk;
    float*       outp= (blockIdx.z == 0) ? g_q : g_kt;

    __shared__ uint32_t Xs[128*XS_STR];
    __shared__ uint32_t Ws[32*WS_STR];

    const int m0 = blockIdx.y * 128;
    const int n0 = blockIdx.x * 128;
    const int t    = threadIdx.x;
    const int warp = t >> 5;
    const int lane = t & 31;
    const int lq   = lane & 3;     // quad lane
    const int lr   = lane >> 2;    // quad row
    const int wm = (warp >> 1) * 32;
    const int wn = (warp & 1) * 64;

    // loader indices
    const int xr = t >> 1;          // 0..127, 2 threads/row
    const int xcb = (t & 1) * 4;    // float4 col base (of 8)
    const int wr = t >> 3;          // 0..31
    const int wcb = t & 7;          // float4 col: wcb + 8j

    float acc[2][8][4] = {};

    for (int k0 = 0; k0 < DD; k0 += 32) {
        const float* xp = X + (size_t)(m0 + xr) * DD + k0;
        #pragma unroll
        for (int j = 0; j < 4; j++) {
            int c = xcb + j;
            float4 f = *(const float4*)(xp + 4*c);
            uint4 u = make_uint4(f2tf32(f.x), f2tf32(f.y), f2tf32(f.z), f2tf32(f.w));
            *(uint4*)&Xs[xr*XS_STR + 4*c] = u;
        }
        const float* wp = W + (size_t)(k0 + wr) * DD + n0;
        #pragma unroll
        for (int j = 0; j < 4; j++) {
            int c = wcb + 8*j;
            float4 f = *(const float4*)(wp + 4*c);
            uint4 u = make_uint4(f2tf32(f.x), f2tf32(f.y), f2tf32(f.z), f2tf32(f.w));
            *(uint4*)&Ws[wr*WS_STR + 4*c] = u;
        }
        __syncthreads();

        #pragma unroll
        for (int ks = 0; ks < 4; ks++) {
            int kb = ks * 8;
            uint32_t a[2][4];
            #pragma unroll
            for (int mt = 0; mt < 2; mt++) {
                int ar = wm + 16*mt + lr;
                a[mt][0] = Xs[ar*XS_STR + kb + lq];
                a[mt][1] = Xs[(ar+8)*XS_STR + kb + lq];
                a[mt][2] = Xs[ar*XS_STR + kb + lq + 4];
                a[mt][3] = Xs[(ar+8)*XS_STR + kb + lq + 4];
            }
            #pragma unroll
            for (int nt = 0; nt < 8; nt++) {
                int bc = wn + 8*nt + lr;
                uint32_t b0 = Ws[(kb + lq)*WS_STR + bc];
                uint32_t b1 = Ws[(kb + 4 + lq)*WS_STR + bc];
                mma_tf32(acc[0][nt], a[0], b0, b1);
                mma_tf32(acc[1][nt], a[1], b0, b1);
            }
        }
        __syncthreads();
    }

    // epilogue: + bias, float2 stores
    #pragma unroll
    for (int nt = 0; nt < 8; nt++) {
        int c = n0 + wn + 8*nt + 2*lq;
        float bx = bia[c], by = bia[c+1];
        #pragma unroll
        for (int mt = 0; mt < 2; mt++) {
            int r = m0 + wm + 16*mt + lr;
            float2 o0 = make_float2(acc[mt][nt][0] + bx, acc[mt][nt][1] + by);
            float2 o1 = make_float2(acc[mt][nt][2] + bx, acc[mt][nt][3] + by);
            *(float2*)(outp + (size_t)r * DD + c) = o0;
            *(float2*)(outp + (size_t)(r+8) * DD + c) = o1;
        }
    }
}

// ---------------------------------------------------------------------------
// Elementwise: kt = softplus(k_raw), v = q + k_raw
// ---------------------------------------------------------------------------
__device__ __forceinline__ float softplus_f(float x) {
    return (x > 15.0f) ? x : log1pf(__expf(x));
}

__global__ __launch_bounds__(256) void fuse_kernel()
{
    int i = blockIdx.x * 256 + threadIdx.x;
    float4 q = ((const float4*)g_q)[i];
    float4 k = ((const float4*)g_kt)[i];
    float4 v, kt;
    v.x = q.x + k.x;  v.y = q.y + k.y;  v.z = q.z + k.z;  v.w = q.w + k.w;
    kt.x = softplus_f(k.x);
    kt.y = softplus_f(k.y);
    kt.z = softplus_f(k.z);
    kt.w = softplus_f(k.w);
    ((float4*)g_v)[i]  = v;
    ((float4*)g_kt)[i] = kt;
}

// ---------------------------------------------------------------------------
// Flash attention, tf32 tensor cores.
// CTA = (64-query tile, head, batch), 256 thr = 8 warps as 4m x 2n.
// Warp tile 16x32 per MMA stage. Q/K/V held as tf32 in smem; S in fp32.
// Query-axis mask -> row forced to -10000 (uniform softmax, matches ref).
// ---------------------------------------------------------------------------
#define QS_STR 68    // [q][d]   uint, A operand (4r+c banks: conflict-free)
#define KT_STR 72    // [d][key] uint, B operand (8k+n banks: conflict-free)
#define VS_STR 72    // [key][d] uint, B operand
#define SS_STR 66    // [q][key] float
#define SMEM_ATTN ((64*QS_STR + 64*KT_STR + 64*VS_STR)*4 + 64*SS_STR*4 + 64*4*4)

__global__ __launch_bounds__(256) void attn_tc(
    const int* __restrict__ amask, float* __restrict__ out)
{
    extern __shared__ float smf[];
    uint32_t* Qs  = (uint32_t*)smf;            // [64][QS_STR]
    uint32_t* KsT = Qs  + 64*QS_STR;           // [64][KT_STR] (d-major)
    uint32_t* Vs  = KsT + 64*KT_STR;           // [64][VS_STR] (key-major)
    float*    Ss  = (float*)(Vs + 64*VS_STR);  // [64][SS_STR]
    float*    msh = Ss  + 64*SS_STR;
    float*    lsh = msh + 64;
    float*    csh = lsh + 64;
    int*      mkf = (int*)(csh + 64);

    const int qt = blockIdx.x, h = blockIdx.y, b = blockIdx.z;
    const int t    = threadIdx.x;
    const int warp = t >> 5;
    const int lane = t & 31;
    const int lq   = lane & 3;
    const int lr   = lane >> 2;
    const int wm = (warp >> 1) * 16;   // query offset of warp's m16 frag
    const int wn = (warp & 1) * 32;    // n offset (key for S, dim for O)
    const int lrow = t >> 2, lv = t & 3;

    if (t < 64) {
        msh[t] = -1e30f;
        lsh[t] = 0.0f;
        mkf[t] = (amask[b*SSL + qt*64 + t] == 0) ? 1 : 0;
    }
    {   // Q tile -> smem (tf32, 1/8 scale folded)
        const float* qp = g_q + ((size_t)(b*SSL + qt*64 + lrow))*DD + h*HDD;
        #pragma unroll
        for (int j = 0; j < 4; j++) {
            int c = lv + 4*j;
            float4 f = *(const float4*)(qp + 4*c);
            uint4 u = make_uint4(f2tf32(f.x*0.125f), f2tf32(f.y*0.125f),
                                 f2tf32(f.z*0.125f), f2tf32(f.w*0.125f));
            *(uint4*)&Qs[lrow*QS_STR + 4*c] = u;
        }
    }
    float accO[4][4] = {};
    __syncthreads();

    for (int k0 = 0; k0 < SSL; k0 += 64) {
        {   // K (transposed, tf32) + V (tf32)
            size_t base = ((size_t)(b*SSL + k0 + lrow))*DD + h*HDD;
            #pragma unroll
            for (int j = 0; j < 4; j++) {
                int c = lv + 4*j;
                float4 kf = *(const float4*)(g_kt + base + 4*c);
                KsT[(4*c+0)*KT_STR + lrow] = f2tf32(kf.x);
                KsT[(4*c+1)*KT_STR + lrow] = f2tf32(kf.y);
                KsT[(4*c+2)*KT_STR + lrow] = f2tf32(kf.z);
                KsT[(4*c+3)*KT_STR + lrow] = f2tf32(kf.w);
                float4 vf = *(const float4*)(g_v + base + 4*c);
                uint4 u = make_uint4(f2tf32(vf.x), f2tf32(vf.y),
                                     f2tf32(vf.z), f2tf32(vf.w));
                *(uint4*)&Vs[lrow*VS_STR + 4*c] = u;
            }
        }
        __syncthreads();

        // S = (Q/8) @ K^T  (64x64, k=64)
        float accS[4][4] = {};
        #pragma unroll
        for (int ks = 0; ks < 8; ks++) {
            int kb = ks * 8;
            uint32_t a[4];
            int ar = wm + lr;
            a[0] = Qs[ar*QS_STR + kb + lq];
            a[1] = Qs[(ar+8)*QS_STR + kb + lq];
            a[2] = Qs[ar*QS_STR + kb + lq + 4];
            a[3] = Qs[(ar+8)*QS_STR + kb + lq + 4];
            #pragma unroll
            for (int nt = 0; nt < 4; nt++) {
                int bc = wn + 8*nt + lr;
                uint32_t b0 = KsT[(kb + lq)*KT_STR + bc];
                uint32_t b1 = KsT[(kb + 4 + lq)*KT_STR + bc];
                mma_tf32(accS[nt], a, b0, b1);
            }
        }
        {   // S frags -> smem (fp32)
            int r0 = wm + lr;
            #pragma unroll
            for (int nt = 0; nt < 4; nt++) {
                int col = wn + 8*nt + 2*lq;
                *(float2*)&Ss[r0*SS_STR + col] = make_float2(accS[nt][0], accS[nt][1]);
                *(float2*)&Ss[(r0+8)*SS_STR + col] = make_float2(accS[nt][2], accS[nt][3]);
            }
        }
        __syncthreads();

        // Online softmax: 4 threads per row, 16 cols each
        {
            const int r = t >> 2, c4 = t & 3;
            const bool masked = (mkf[r] != 0);
            float sv[16], mx = -1e30f;
            #pragma unroll
            for (int ii = 0; ii < 16; ii++) {
                float s = Ss[r*SS_STR + c4*16 + ii];
                if (masked) s = -10000.0f;
                sv[ii] = s;
                mx = fmaxf(mx, s);
            }
            mx = fmaxf(mx, __shfl_xor_sync(0xffffffffu, mx, 1));
            mx = fmaxf(mx, __shfl_xor_sync(0xffffffffu, mx, 2));
            float mold = msh[r];
            float mnew = fmaxf(mold, mx);
            float sum = 0.0f;
            #pragma unroll
            for (int ii = 0; ii < 16; ii++) {
                float p = __expf(sv[ii] - mnew);
                Ss[r*SS_STR + c4*16 + ii] = p;
                sum += p;
            }
            sum += __shfl_xor_sync(0xffffffffu, sum, 1);
            sum += __shfl_xor_sync(0xffffffffu, sum, 2);
            if (c4 == 0) {
                float corr = __expf(mold - mnew);
                csh[r] = corr;
                msh[r] = mnew;
                lsh[r] = lsh[r] * corr + sum;
            }
        }
        __syncthreads();

        // Rescale O, then O += P @ V
        {
            float cr0 = csh[wm + lr];
            float cr1 = csh[wm + 8 + lr];
            #pragma unroll
            for (int nt = 0; nt < 4; nt++) {
                accO[nt][0] *= cr0; accO[nt][1] *= cr0;
                accO[nt][2] *= cr1; accO[nt][3] *= cr1;
            }
        }
        #pragma unroll
        for (int ks = 0; ks < 8; ks++) {
            int kb = ks * 8;
            uint32_t a[4];
            int ar = wm + lr;
            a[0] = f2tf32(Ss[ar*SS_STR + kb + lq]);
            a[1] = f2tf32(Ss[(ar+8)*SS_STR + kb + lq]);
            a[2] = f2tf32(Ss[ar*SS_STR + kb + lq + 4]);
            a[3] = f2tf32(Ss[(ar+8)*SS_STR + kb + lq + 4]);
            #pragma unroll
            for (int nt = 0; nt < 4; nt++) {
                int bc = wn + 8*nt + lr;
                uint32_t b0 = Vs[(kb + lq)*VS_STR + bc];
                uint32_t b1 = Vs[(kb + 4 + lq)*VS_STR + bc];
                mma_tf32(accO[nt], a, b0, b1);
            }
        }
        __syncthreads();
    }

    // Final: O / l, write [B,S,H*HD]
    {
        int r0 = wm + lr, r1 = r0 + 8;
        float li0 = 1.0f / lsh[r0];
        float li1 = 1.0f / lsh[r1];
        size_t row0 = (size_t)(b*SSL + qt*64 + r0) * DD;
        size_t row1 = (size_t)(b*SSL + qt*64 + r1) * DD;
        #pragma unroll
        for (int nt = 0; nt < 4; nt++) {
            int col = h*HDD + wn + 8*nt + 2*lq;
            *(float2*)(out + row0 + col) = make_float2(accO[nt][0]*li0, accO[nt][1]*li0);
            *(float2*)(out + row1 + col) = make_float2(accO[nt][2]*li1, accO[nt][3]*li1);
        }
    }
}

// ---------------------------------------------------------------------------
extern "C" void kernel_launch(void* const* d_in, const int* in_sizes, int n_in,
                              void* d_out, int out_size)
{
    const float* X     = (const float*)d_in[0];
    const int*   amask = (const int*)  d_in[1];
    const float* Wq    = (const float*)d_in[2];
    const float* bq    = (const float*)d_in[3];
    const float* Wk    = (const float*)d_in[4];
    const float* bk    = (const float*)d_in[5];
    float*       out   = (float*)d_out;

    proj_tc<<<dim3(DD/128, MSZ/128, 2), 256>>>(X, Wq, bq, Wk, bk);
    fuse_kernel<<<(MSZ*DD/4)/256, 256>>>();
    cudaFuncSetAttribute(attn_tc,
                         cudaFuncAttributeMaxDynamicSharedMemorySize, SMEM_ATTN);
    attn_tc<<<dim3(SSL/64, HH, BB), 256, SMEM_ATTN>>>(amask, out);
}